// round 14
// baseline (speedup 1.0000x reference)
#include <cuda_runtime.h>
#include <math.h>

#define Bb 32
#define Tt 64
#define Kk 5
#define Vv 32000
#define DE 300
#define DA 300
#define DI 2048
#define Hh 512
#define FH 2048              // 4*H
#define HOFF (DE + DI + DA)  // 2648, row offset of h-part in lstm_kernel
#define BT (Bb * Tt)         // 2048

// ---------------- scratch (static device globals; no allocation) -------------
__device__ float g_mattr[Bb * DA];        // mean attribute embedding per batch
__device__ float g_preb[Bb * FH];         // bias + feats @ W_feats  [B,4H]
__device__ float g_zpre[BT * FH];         // + word_emb @ W_word     [B*T,4H] (16MB)
__device__ float g_hbuf[2][Bb * Hh];      // ping-pong h state
__device__ float g_c[Bb * Hh];            // cell state
__device__ float g_hseq[BT * Hh];         // masked h outputs (4MB)

// ---------------- f32x2 packed helpers (sm_103a FFMA2 path) ------------------
__device__ __forceinline__ unsigned long long pk2(float lo, float hi) {
    unsigned long long r;
    asm("mov.b64 %0, {%1, %2};" : "=l"(r) : "f"(lo), "f"(hi));
    return r;
}
__device__ __forceinline__ void fma2(unsigned long long& d,
                                     unsigned long long a,
                                     unsigned long long b) {
    asm("fma.rn.f32x2 %0, %1, %2, %0;" : "+l"(d) : "l"(a), "l"(b));
}
__device__ __forceinline__ float lo2(unsigned long long v) {
    return __uint_as_float((unsigned)(v & 0xffffffffull));
}
__device__ __forceinline__ float hi2(unsigned long long v) {
    return __uint_as_float((unsigned)(v >> 32));
}

// ---------------- kernel 0: init states, bias broadcast, mean attr -----------
__global__ void k_init(const int* __restrict__ topk,
                       const float* __restrict__ attr_emb,
                       const float* __restrict__ bias) {
    int idx = blockIdx.x * 256 + threadIdx.x;           // 0 .. Bb*FH-1
    g_preb[idx] = bias[idx & (FH - 1)];
    if (idx < Bb * Hh) { g_hbuf[0][idx] = 0.f; g_c[idx] = 0.f; }
    if (idx < Bb * DA) {
        int b = idx / DA, d = idx - b * DA;
        float s = 0.f;
#pragma unroll
        for (int k = 0; k < Kk; k++)
            s += attr_emb[topk[b * Kk + k] * DA + d];
        g_mattr[idx] = s * (1.0f / Kk);
    }
}

// ---------------- kernel 1: g_preb += [img, mean_attr] @ W -------------------
// grid (16 j-tiles of 128, 4 b-groups of 8), 128 threads
__global__ void __launch_bounds__(128) k_preb(const float* __restrict__ img,
                                              const float* __restrict__ Wl) {
    __shared__ float sm[8][32];
    int j = blockIdx.x * 128 + threadIdx.x;
    int b0 = blockIdx.y * 8;
    float acc[8];
#pragma unroll
    for (int b = 0; b < 8; b++) acc[b] = 0.f;

    // segment 1: image features, W rows [DE, DE+DI)
    for (int d0 = 0; d0 < DI; d0 += 32) {
#pragma unroll
        for (int i = 0; i < 2; i++) {
            int e = threadIdx.x + i * 128;
            int bb = e >> 5, dc = e & 31;
            sm[bb][dc] = img[(b0 + bb) * DI + d0 + dc];
        }
        __syncthreads();
#pragma unroll 4
        for (int dc = 0; dc < 32; dc++) {
            float w = Wl[(size_t)(DE + d0 + dc) * FH + j];
#pragma unroll
            for (int b = 0; b < 8; b++) acc[b] += sm[b][dc] * w;
        }
        __syncthreads();
    }
    // segment 2: mean attr, W rows [DE+DI, DE+DI+DA), DA=300 (remainder 12)
    for (int d0 = 0; d0 < DA; d0 += 32) {
        int lim = DA - d0; if (lim > 32) lim = 32;
#pragma unroll
        for (int i = 0; i < 2; i++) {
            int e = threadIdx.x + i * 128;
            int bb = e >> 5, dc = e & 31;
            sm[bb][dc] = (dc < lim) ? g_mattr[(b0 + bb) * DA + d0 + dc] : 0.f;
        }
        __syncthreads();
        for (int dc = 0; dc < lim; dc++) {
            float w = Wl[(size_t)(DE + DI + d0 + dc) * FH + j];
#pragma unroll
            for (int b = 0; b < 8; b++) acc[b] += sm[b][dc] * w;
        }
        __syncthreads();
    }
#pragma unroll
    for (int b = 0; b < 8; b++)
        g_preb[(b0 + b) * FH + j] += acc[b];
}

// ---------------- kernel 2: g_zpre = gather(word_emb) @ W_word + g_preb ------
// M=2048 rows (b*T+t), N=2048, K=300. BM=BN=64, BK=20. grid (32,32), 256 thr.
__global__ void __launch_bounds__(256) k_zpre(const int* __restrict__ seq,
                                              const float* __restrict__ wemb,
                                              const float* __restrict__ Wl) {
    __shared__ float As[20 * 68];   // [k][m], padded pitch 68
    __shared__ float Bs[20 * 64];   // [k][n]
    __shared__ int sidx[64];
    int tid = threadIdx.x;
    int mbase = blockIdx.y * 64, nbase = blockIdx.x * 64;
    if (tid < 64) sidx[tid] = seq[mbase + tid];

    float acc[4][4];
#pragma unroll
    for (int i = 0; i < 4; i++)
#pragma unroll
        for (int j = 0; j < 4; j++) acc[i][j] = 0.f;

    int tm = (tid >> 4) * 4, tn = (tid & 15) * 4;

    for (int k0 = 0; k0 < 300; k0 += 20) {
        __syncthreads();
#pragma unroll
        for (int i = 0; i < 5; i++) {
            int e = tid + i * 256;
            int m = e / 20, kk = e - m * 20;
            As[kk * 68 + m] = wemb[(size_t)sidx[m] * DE + k0 + kk];
        }
#pragma unroll
        for (int i = 0; i < 5; i++) {
            int e = tid + i * 256;
            int kk = e >> 6, n = e & 63;
            Bs[kk * 64 + n] = Wl[(size_t)(k0 + kk) * FH + nbase + n];
        }
        __syncthreads();
#pragma unroll
        for (int kk = 0; kk < 20; kk++) {
            float4 a = *(const float4*)&As[kk * 68 + tm];
            float4 b = *(const float4*)&Bs[kk * 64 + tn];
            acc[0][0] += a.x * b.x; acc[0][1] += a.x * b.y; acc[0][2] += a.x * b.z; acc[0][3] += a.x * b.w;
            acc[1][0] += a.y * b.x; acc[1][1] += a.y * b.y; acc[1][2] += a.y * b.z; acc[1][3] += a.y * b.w;
            acc[2][0] += a.z * b.x; acc[2][1] += a.z * b.y; acc[2][2] += a.z * b.z; acc[2][3] += a.z * b.w;
            acc[3][0] += a.w * b.x; acc[3][1] += a.w * b.y; acc[3][2] += a.w * b.z; acc[3][3] += a.w * b.w;
        }
    }
#pragma unroll
    for (int mi = 0; mi < 4; mi++) {
        int row = mbase + tm + mi;
        int b = row >> 6;  // row / T
        float4 pv = *(const float4*)&g_preb[b * FH + nbase + tn];
        float4 v = { acc[mi][0] + pv.x, acc[mi][1] + pv.y,
                     acc[mi][2] + pv.z, acc[mi][3] + pv.w };
        *(float4*)&g_zpre[(size_t)row * FH + nbase + tn] = v;
    }
}

// ---------------- kernel 3 (x64): one LSTM step -------------------------------
// z = zpre[:,t,:] + h @ W_h ; gates ; update c,h ; write masked h_seq.
// grid (32 u-tiles of 16 units, 4 b-groups of 8), 256 threads.
// h ping-pongs between g_hbuf[t&1] (read) and g_hbuf[(t+1)&1] (write).
__global__ void __launch_bounds__(256) k_step(const float* __restrict__ Wl,
                                              const int* __restrict__ lengths,
                                              int t) {
    __shared__ float h_s[Hh * 8];        // [k][b] transposed, 16KB
    __shared__ float zred[4 * 8 * 64];   // [kslice][b][jj], 8KB
    const float* hin = g_hbuf[t & 1];
    float* hout = g_hbuf[(t + 1) & 1];

    int ut = blockIdx.x;
    int b0 = blockIdx.y * 8;
    int tid = threadIdx.x;

#pragma unroll
    for (int i = 0; i < 16; i++) {
        int e = tid + i * 256;
        int b = e >> 9, k = e & 511;
        h_s[k * 8 + b] = hin[(b0 + b) * Hh + k];
    }
    __syncthreads();

    int jj = tid & 63, ks = tid >> 6;
    int gate = jj >> 4, uu = jj & 15;
    int jcol = gate * Hh + ut * 16 + uu;
    int kb = ks * 128;
    const float* wp = Wl + (size_t)(HOFF + kb) * FH + jcol;

    unsigned long long acc[4] = {0ull, 0ull, 0ull, 0ull};
#pragma unroll 4
    for (int kk = 0; kk < 128; kk++) {
        float w = wp[(size_t)kk * FH];
        unsigned long long wd = pk2(w, w);
        const unsigned long long* hp =
            (const unsigned long long*)&h_s[(kb + kk) * 8];
        fma2(acc[0], hp[0], wd);
        fma2(acc[1], hp[1], wd);
        fma2(acc[2], hp[2], wd);
        fma2(acc[3], hp[3], wd);
    }
    float* zr = &zred[(ks * 8) * 64];
#pragma unroll
    for (int bp = 0; bp < 4; bp++) {
        zr[(2 * bp) * 64 + jj] = lo2(acc[bp]);
        zr[(2 * bp + 1) * 64 + jj] = hi2(acc[bp]);
    }
    __syncthreads();

    if (tid < 128) {
        int b = tid >> 4, u16 = tid & 15;
        int u = ut * 16 + u16;
        float zi = 0.f, zf = 0.f, zg = 0.f, zo = 0.f;
#pragma unroll
        for (int s = 0; s < 4; s++) {
            const float* q = &zred[(s * 8 + b) * 64];
            zi += q[0 * 16 + u16];
            zf += q[1 * 16 + u16];
            zg += q[2 * 16 + u16];
            zo += q[3 * 16 + u16];
        }
        int row = (b0 + b) * Tt + t;
        const float* zp = &g_zpre[(size_t)row * FH];
        zi += zp[0 * Hh + u];
        zf += zp[1 * Hh + u];
        zg += zp[2 * Hh + u];
        zo += zp[3 * Hh + u];

        int ci = (b0 + b) * Hh + u;
        float c = g_c[ci];
        float si = 1.f / (1.f + expf(-zi));
        float sf = 1.f / (1.f + expf(-zf));
        float so = 1.f / (1.f + expf(-zo));
        float c2 = sf * c + si * tanhf(zg);
        float h2 = so * tanhf(c2);
        g_c[ci] = c2;
        hout[ci] = h2;
        g_hseq[(size_t)row * Hh + u] = (t < lengths[b0 + b]) ? h2 : 0.f;
    }
}

// ---------------- kernel 4: logits = h_seq @ W_logits + b --------------------
// M=2048, N=32000, K=512. BM=128, BN=64, BK=16. grid (500,16), 256 threads.
// Inner product uses packed f32x2 FMA (m-row pairs packed, b duplicated).
__global__ void __launch_bounds__(256) k_logits(const float* __restrict__ Wlog,
                                                const float* __restrict__ blog,
                                                float* __restrict__ out) {
    __shared__ float As[16 * 132];  // [k][m], pitch 132 (16B-aligned rows, bank-spread)
    __shared__ float Bs[16 * 64];   // [k][n]
    int tid = threadIdx.x;
    int nb = blockIdx.x * 64, mb = blockIdx.y * 128;
    int tm = (tid >> 4) * 8, tn = (tid & 15) * 4;

    unsigned long long acc[4][4];
#pragma unroll
    for (int i = 0; i < 4; i++)
#pragma unroll
        for (int j = 0; j < 4; j++) acc[i][j] = 0ull;

    for (int k0 = 0; k0 < Hh; k0 += 16) {
        __syncthreads();
#pragma unroll
        for (int i = 0; i < 8; i++) {
            int e = tid + i * 256;
            int m = e >> 4, kk = e & 15;
            As[kk * 132 + m] = g_hseq[(size_t)(mb + m) * Hh + k0 + kk];
        }
#pragma unroll
        for (int i = 0; i < 4; i++) {
            int e = tid + i * 256;
            int kk = e >> 6, n = e & 63;
            Bs[kk * 64 + n] = Wlog[(size_t)(k0 + kk) * Vv + nb + n];
        }
        __syncthreads();
#pragma unroll
        for (int kk = 0; kk < 16; kk++) {
            const unsigned long long* ap =
                (const unsigned long long*)&As[kk * 132 + tm];
            unsigned long long a0 = ap[0], a1 = ap[1], a2 = ap[2], a3 = ap[3];
            float4 bv = *(const float4*)&Bs[kk * 64 + tn];
            unsigned long long b0 = pk2(bv.x, bv.x), b1 = pk2(bv.y, bv.y);
            unsigned long long b2 = pk2(bv.z, bv.z), b3 = pk2(bv.w, bv.w);
            fma2(acc[0][0], a0, b0); fma2(acc[0][1], a0, b1);
            fma2(acc[0][2], a0, b2); fma2(acc[0][3], a0, b3);
            fma2(acc[1][0], a1, b0); fma2(acc[1][1], a1, b1);
            fma2(acc[1][2], a1, b2); fma2(acc[1][3], a1, b3);
            fma2(acc[2][0], a2, b0); fma2(acc[2][1], a2, b1);
            fma2(acc[2][2], a2, b2); fma2(acc[2][3], a2, b3);
            fma2(acc[3][0], a3, b0); fma2(acc[3][1], a3, b1);
            fma2(acc[3][2], a3, b2); fma2(acc[3][3], a3, b3);
        }
    }
    float4 bias = *(const float4*)&blog[nb + tn];
#pragma unroll
    for (int mp = 0; mp < 4; mp++) {
        int r0 = mb + tm + 2 * mp;
        float4 v0 = { lo2(acc[mp][0]) + bias.x, lo2(acc[mp][1]) + bias.y,
                      lo2(acc[mp][2]) + bias.z, lo2(acc[mp][3]) + bias.w };
        float4 v1 = { hi2(acc[mp][0]) + bias.x, hi2(acc[mp][1]) + bias.y,
                      hi2(acc[mp][2]) + bias.z, hi2(acc[mp][3]) + bias.w };
        *(float4*)&out[(size_t)r0 * Vv + nb + tn] = v0;
        *(float4*)&out[(size_t)(r0 + 1) * Vv + nb + tn] = v1;
    }
}

// ---------------- kernel 5: row-wise argmax (first-max tie-break) ------------
__global__ void __launch_bounds__(256) k_argmax(const float* __restrict__ logits,
                                                float* __restrict__ out_arg) {
    __shared__ float sv[256];
    __shared__ int si[256];
    int row = blockIdx.x;
    const float* p = logits + (size_t)row * Vv;
    float best = -INFINITY;
    int bi = 0;
    for (int c = threadIdx.x; c < Vv; c += 256) {
        float v = p[c];
        if (v > best) { best = v; bi = c; }
    }
    sv[threadIdx.x] = best;
    si[threadIdx.x] = bi;
    __syncthreads();
    for (int s = 128; s > 0; s >>= 1) {
        if (threadIdx.x < s) {
            float v2 = sv[threadIdx.x + s];
            int i2 = si[threadIdx.x + s];
            if (v2 > sv[threadIdx.x] ||
                (v2 == sv[threadIdx.x] && i2 < si[threadIdx.x])) {
                sv[threadIdx.x] = v2;
                si[threadIdx.x] = i2;
            }
        }
        __syncthreads();
    }
    if (threadIdx.x == 0) out_arg[row] = (float)si[0];
}

// ---------------- launch ------------------------------------------------------
extern "C" void kernel_launch(void* const* d_in, const int* in_sizes, int n_in,
                              void* d_out, int out_size) {
    const int*   topk = (const int*)d_in[0];     // [B,K]
    const float* img  = (const float*)d_in[1];   // [B,DI]
    const int*   seq  = (const int*)d_in[2];     // [B,T]
    const int*   len  = (const int*)d_in[3];     // [B]
    const float* wemb = (const float*)d_in[4];   // [V,DE]
    const float* aemb = (const float*)d_in[5];   // [1000,DA]
    const float* Wl   = (const float*)d_in[6];   // [DE+DI+DA+H, 4H]
    const float* bl   = (const float*)d_in[7];   // [4H]
    const float* Wlog = (const float*)d_in[8];   // [H,V]
    const float* blog = (const float*)d_in[9];   // [V]
    float* out = (float*)d_out;

    k_init<<<(Bb * FH) / 256, 256>>>(topk, aemb, bl);
    k_preb<<<dim3(FH / 128, 4), 128>>>(img, Wl);
    k_zpre<<<dim3(FH / 64, BT / 64), 256>>>(seq, wemb, Wl);
    for (int t = 0; t < Tt; t++)
        k_step<<<dim3(Hh / 16, Bb / 8), 256>>>(Wl, len, t);
    k_logits<<<dim3(Vv / 64, BT / 128), 256>>>(Wlog, blog, out);
    if (out_size >= (long long)BT * Vv + BT)
        k_argmax<<<BT, 256>>>(out, out + (size_t)BT * Vv);
}

// round 15
// speedup vs baseline: 1.0753x; 1.0753x over previous
#include <cuda_runtime.h>
#include <math.h>

#define Bb 32
#define Tt 64
#define Kk 5
#define Vv 32000
#define DE 300
#define DA 300
#define DI 2048
#define Hh 512
#define FH 2048              // 4*H
#define HOFF (DE + DI + DA)  // 2648, row offset of h-part in lstm_kernel
#define BT (Bb * Tt)         // 2048
#define NBLK 128             // persistent LSTM blocks (<=148 SMs -> co-resident)

// ---------------- scratch (static device globals; no allocation) -------------
__device__ float g_mattr[Bb * DA];        // mean attribute embedding per batch
__device__ float g_preb[Bb * FH];         // bias + feats @ W_feats  [B,4H]
__device__ float g_zpre[BT * FH];         // + word_emb @ W_word     [B*T,4H] (16MB)
__device__ __align__(16) float g_hT[2][Hh * Bb];  // ping-pong h, TRANSPOSED [k][b]
__device__ float g_hseq[BT * Hh];         // masked h outputs (4MB)
__device__ unsigned g_barctr;             // grid barrier counter (reset in k_init)

// ---------------- f32x2 packed helpers (sm_103a FFMA2 path) ------------------
__device__ __forceinline__ unsigned long long pk2(float lo, float hi) {
    unsigned long long r;
    asm("mov.b64 %0, {%1, %2};" : "=l"(r) : "f"(lo), "f"(hi));
    return r;
}
__device__ __forceinline__ void fma2(unsigned long long& d,
                                     unsigned long long a,
                                     unsigned long long b) {
    asm("fma.rn.f32x2 %0, %1, %2, %0;" : "+l"(d) : "l"(a), "l"(b));
}
__device__ __forceinline__ float lo2(unsigned long long v) {
    return __uint_as_float((unsigned)(v & 0xffffffffull));
}
__device__ __forceinline__ float hi2(unsigned long long v) {
    return __uint_as_float((unsigned)(v >> 32));
}

// ---------------- kernel 0: init states, bias broadcast, mean attr -----------
__global__ void k_init(const int* __restrict__ topk,
                       const float* __restrict__ attr_emb,
                       const float* __restrict__ bias) {
    int idx = blockIdx.x * 256 + threadIdx.x;           // 0 .. Bb*FH-1
    g_preb[idx] = bias[idx & (FH - 1)];
    if (idx < Hh * Bb) g_hT[0][idx] = 0.f;
    if (idx == 0) g_barctr = 0u;
    if (idx < Bb * DA) {
        int b = idx / DA, d = idx - b * DA;
        float s = 0.f;
#pragma unroll
        for (int k = 0; k < Kk; k++)
            s += attr_emb[topk[b * Kk + k] * DA + d];
        g_mattr[idx] = s * (1.0f / Kk);
    }
}

// ---------------- kernel 1: g_preb += [img, mean_attr] @ W -------------------
__global__ void __launch_bounds__(128) k_preb(const float* __restrict__ img,
                                              const float* __restrict__ Wl) {
    __shared__ float sm[8][32];
    int j = blockIdx.x * 128 + threadIdx.x;
    int b0 = blockIdx.y * 8;
    float acc[8];
#pragma unroll
    for (int b = 0; b < 8; b++) acc[b] = 0.f;

    for (int d0 = 0; d0 < DI; d0 += 32) {
#pragma unroll
        for (int i = 0; i < 2; i++) {
            int e = threadIdx.x + i * 128;
            int bb = e >> 5, dc = e & 31;
            sm[bb][dc] = img[(b0 + bb) * DI + d0 + dc];
        }
        __syncthreads();
#pragma unroll 4
        for (int dc = 0; dc < 32; dc++) {
            float w = Wl[(size_t)(DE + d0 + dc) * FH + j];
#pragma unroll
            for (int b = 0; b < 8; b++) acc[b] += sm[b][dc] * w;
        }
        __syncthreads();
    }
    for (int d0 = 0; d0 < DA; d0 += 32) {
        int lim = DA - d0; if (lim > 32) lim = 32;
#pragma unroll
        for (int i = 0; i < 2; i++) {
            int e = threadIdx.x + i * 128;
            int bb = e >> 5, dc = e & 31;
            sm[bb][dc] = (dc < lim) ? g_mattr[(b0 + bb) * DA + d0 + dc] : 0.f;
        }
        __syncthreads();
        for (int dc = 0; dc < lim; dc++) {
            float w = Wl[(size_t)(DE + DI + d0 + dc) * FH + j];
#pragma unroll
            for (int b = 0; b < 8; b++) acc[b] += sm[b][dc] * w;
        }
        __syncthreads();
    }
#pragma unroll
    for (int b = 0; b < 8; b++)
        g_preb[(b0 + b) * FH + j] += acc[b];
}

// ---------------- kernel 2: g_zpre = gather(word_emb) @ W_word + g_preb ------
__global__ void __launch_bounds__(256) k_zpre(const int* __restrict__ seq,
                                              const float* __restrict__ wemb,
                                              const float* __restrict__ Wl) {
    __shared__ float As[20 * 68];
    __shared__ float Bs[20 * 64];
    __shared__ int sidx[64];
    int tid = threadIdx.x;
    int mbase = blockIdx.y * 64, nbase = blockIdx.x * 64;
    if (tid < 64) sidx[tid] = seq[mbase + tid];

    float acc[4][4];
#pragma unroll
    for (int i = 0; i < 4; i++)
#pragma unroll
        for (int j = 0; j < 4; j++) acc[i][j] = 0.f;

    int tm = (tid >> 4) * 4, tn = (tid & 15) * 4;

    for (int k0 = 0; k0 < 300; k0 += 20) {
        __syncthreads();
#pragma unroll
        for (int i = 0; i < 5; i++) {
            int e = tid + i * 256;
            int m = e / 20, kk = e - m * 20;
            As[kk * 68 + m] = wemb[(size_t)sidx[m] * DE + k0 + kk];
        }
#pragma unroll
        for (int i = 0; i < 5; i++) {
            int e = tid + i * 256;
            int kk = e >> 6, n = e & 63;
            Bs[kk * 64 + n] = Wl[(size_t)(k0 + kk) * FH + nbase + n];
        }
        __syncthreads();
#pragma unroll
        for (int kk = 0; kk < 20; kk++) {
            float4 a = *(const float4*)&As[kk * 68 + tm];
            float4 b = *(const float4*)&Bs[kk * 64 + tn];
            acc[0][0] += a.x * b.x; acc[0][1] += a.x * b.y; acc[0][2] += a.x * b.z; acc[0][3] += a.x * b.w;
            acc[1][0] += a.y * b.x; acc[1][1] += a.y * b.y; acc[1][2] += a.y * b.z; acc[1][3] += a.y * b.w;
            acc[2][0] += a.z * b.x; acc[2][1] += a.z * b.y; acc[2][2] += a.z * b.z; acc[2][3] += a.z * b.w;
            acc[3][0] += a.w * b.x; acc[3][1] += a.w * b.y; acc[3][2] += a.w * b.z; acc[3][3] += a.w * b.w;
        }
    }
#pragma unroll
    for (int mi = 0; mi < 4; mi++) {
        int row = mbase + tm + mi;
        int b = row >> 6;
        float4 pv = *(const float4*)&g_preb[b * FH + nbase + tn];
        float4 v = { acc[mi][0] + pv.x, acc[mi][1] + pv.y,
                     acc[mi][2] + pv.z, acc[mi][3] + pv.w };
        *(float4*)&g_zpre[(size_t)row * FH + nbase + tn] = v;
    }
}

// ---------------- kernel 3: PERSISTENT LSTM (all 64 steps, one launch) -------
// 128 blocks x 256 threads; block owns 4 units x 4 gates (16 cols of FH).
// W_h slice lives in registers (32/thread). h ping-pongs in global, TRANSPOSED
// [k][b] so staging loads are pure float4 copies and compute reads packed
// batch-pairs for f32x2 FMA. One software grid barrier per step.
// dyn smem: h_s 512*32 f32 (64KB) + zred 256 rows * 17 u64 (34KB) = 100352 B
#define ZPITCH 17  // u64 pitch per (c,ks) row: kills bank conflicts
__device__ __forceinline__ void grid_bar(int tid, unsigned target) {
    __threadfence();
    __syncthreads();
    if (tid == 0) {
        atomicAdd(&g_barctr, 1u);
        while (*((volatile unsigned*)&g_barctr) < target) __nanosleep(32);
        __threadfence();
    }
    __syncthreads();
}

__global__ void __launch_bounds__(256, 1) k_lstm(const float* __restrict__ Wl,
                                                 const int* __restrict__ lengths) {
    extern __shared__ float smdyn[];
    float* h_s = smdyn;                                  // [512][32]
    unsigned long long* zred = (unsigned long long*)(smdyn + Hh * Bb);

    int tid = threadIdx.x, blk = blockIdx.x;
    int c = tid & 15, ks = tid >> 4;                     // col-in-block, k-slice
    int gg = c >> 2, uu = c & 3;
    int jcol = gg * Hh + blk * 4 + uu;                   // column in FH
    int kb = ks * 32;                                    // k-slice base

    // preload W_h slice into registers (once; W_h read from DRAM exactly once)
    float w[32];
#pragma unroll
    for (int i = 0; i < 32; i++)
        w[i] = Wl[(size_t)(HOFF + kb + i) * FH + jcol];

    // fusion-thread state (tid < 128): unit fu, batch fb, c-state in register
    int fu = tid >> 5, fb = tid & 31;
    int u = blk * 4 + fu;
    float cstate = 0.f;
    int mylen = (tid < 128) ? lengths[fb] : 0;

    const float* zf = (const float*)zred;                // float view of partials

    for (int t = 0; t < Tt; t++) {
        // ---- stage h (transposed, packed) into smem: linear float4 copy ----
        const float4* src = (const float4*)g_hT[t & 1];
        float4* dst = (float4*)h_s;
#pragma unroll
        for (int i = 0; i < 16; i++)
            dst[tid + i * 256] = src[tid + i * 256];
        __syncthreads();

        // ---- compute partial z: 16 batch-pairs, k-slice of 32, f32x2 FMA ----
        unsigned long long acc[16];
#pragma unroll
        for (int bp = 0; bp < 16; bp++) acc[bp] = 0ull;
#pragma unroll
        for (int kk = 0; kk < 32; kk++) {
            unsigned long long wd = pk2(w[kk], w[kk]);
            const ulonglong2* hr = (const ulonglong2*)(h_s + (kb + kk) * Bb);
#pragma unroll
            for (int i = 0; i < 8; i++) {
                ulonglong2 hv = hr[i];
                fma2(acc[2 * i], hv.x, wd);
                fma2(acc[2 * i + 1], hv.y, wd);
            }
        }
        unsigned long long* zr = zred + (size_t)(c * 16 + ks) * ZPITCH;
#pragma unroll
        for (int bp = 0; bp < 16; bp++) zr[bp] = acc[bp];
        __syncthreads();

        // ---- gate fusion: 128 threads = 4 units x 32 batches ----
        if (tid < 128) {
            const float* zp = g_zpre + (size_t)(fb * Tt + t) * FH;
            float s[4];
#pragma unroll
            for (int g = 0; g < 4; g++) {
                float a = 0.f;
                int base = ((g * 4 + fu) * 16) * (2 * ZPITCH) + fb;
#pragma unroll
                for (int k2 = 0; k2 < 16; k2++)
                    a += zf[base + k2 * (2 * ZPITCH)];
                s[g] = a + zp[g * Hh + u];
            }
            float si = 1.f / (1.f + expf(-s[0]));
            float sf = 1.f / (1.f + expf(-s[1]));
            float so = 1.f / (1.f + expf(-s[3]));
            cstate = sf * cstate + si * tanhf(s[2]);
            float h2 = so * tanhf(cstate);
            g_hT[(t + 1) & 1][u * Bb + fb] = h2;         // transposed for next step
            g_hseq[(size_t)(fb * Tt + t) * Hh + u] = (t < mylen) ? h2 : 0.f;
        }

        if (t != Tt - 1) grid_bar(tid, (unsigned)(NBLK * (t + 1)));
    }
}

// ---------------- kernel 4: logits = h_seq @ W_logits + b --------------------
__global__ void __launch_bounds__(256) k_logits(const float* __restrict__ Wlog,
                                                const float* __restrict__ blog,
                                                float* __restrict__ out) {
    __shared__ float As[16 * 132];
    __shared__ float Bs[16 * 64];
    int tid = threadIdx.x;
    int nb = blockIdx.x * 64, mb = blockIdx.y * 128;
    int tm = (tid >> 4) * 8, tn = (tid & 15) * 4;

    unsigned long long acc[4][4];
#pragma unroll
    for (int i = 0; i < 4; i++)
#pragma unroll
        for (int j = 0; j < 4; j++) acc[i][j] = 0ull;

    for (int k0 = 0; k0 < Hh; k0 += 16) {
        __syncthreads();
#pragma unroll
        for (int i = 0; i < 8; i++) {
            int e = tid + i * 256;
            int m = e >> 4, kk = e & 15;
            As[kk * 132 + m] = g_hseq[(size_t)(mb + m) * Hh + k0 + kk];
        }
#pragma unroll
        for (int i = 0; i < 4; i++) {
            int e = tid + i * 256;
            int kk = e >> 6, n = e & 63;
            Bs[kk * 64 + n] = Wlog[(size_t)(k0 + kk) * Vv + nb + n];
        }
        __syncthreads();
#pragma unroll
        for (int kk = 0; kk < 16; kk++) {
            const unsigned long long* ap =
                (const unsigned long long*)&As[kk * 132 + tm];
            unsigned long long a0 = ap[0], a1 = ap[1], a2 = ap[2], a3 = ap[3];
            float4 bv = *(const float4*)&Bs[kk * 64 + tn];
            unsigned long long b0 = pk2(bv.x, bv.x), b1 = pk2(bv.y, bv.y);
            unsigned long long b2 = pk2(bv.z, bv.z), b3 = pk2(bv.w, bv.w);
            fma2(acc[0][0], a0, b0); fma2(acc[0][1], a0, b1);
            fma2(acc[0][2], a0, b2); fma2(acc[0][3], a0, b3);
            fma2(acc[1][0], a1, b0); fma2(acc[1][1], a1, b1);
            fma2(acc[1][2], a1, b2); fma2(acc[1][3], a1, b3);
            fma2(acc[2][0], a2, b0); fma2(acc[2][1], a2, b1);
            fma2(acc[2][2], a2, b2); fma2(acc[2][3], a2, b3);
            fma2(acc[3][0], a3, b0); fma2(acc[3][1], a3, b1);
            fma2(acc[3][2], a3, b2); fma2(acc[3][3], a3, b3);
        }
    }
    float4 bias = *(const float4*)&blog[nb + tn];
#pragma unroll
    for (int mp = 0; mp < 4; mp++) {
        int r0 = mb + tm + 2 * mp;
        float4 v0 = { lo2(acc[mp][0]) + bias.x, lo2(acc[mp][1]) + bias.y,
                      lo2(acc[mp][2]) + bias.z, lo2(acc[mp][3]) + bias.w };
        float4 v1 = { hi2(acc[mp][0]) + bias.x, hi2(acc[mp][1]) + bias.y,
                      hi2(acc[mp][2]) + bias.z, hi2(acc[mp][3]) + bias.w };
        *(float4*)&out[(size_t)r0 * Vv + nb + tn] = v0;
        *(float4*)&out[(size_t)(r0 + 1) * Vv + nb + tn] = v1;
    }
}

// ---------------- kernel 5: row-wise argmax (first-max tie-break) ------------
__global__ void __launch_bounds__(256) k_argmax(const float* __restrict__ logits,
                                                float* __restrict__ out_arg) {
    __shared__ float sv[256];
    __shared__ int si[256];
    int row = blockIdx.x;
    const float* p = logits + (size_t)row * Vv;
    float best = -INFINITY;
    int bi = 0;
    for (int c = threadIdx.x; c < Vv; c += 256) {
        float v = p[c];
        if (v > best) { best = v; bi = c; }
    }
    sv[threadIdx.x] = best;
    si[threadIdx.x] = bi;
    __syncthreads();
    for (int s = 128; s > 0; s >>= 1) {
        if (threadIdx.x < s) {
            float v2 = sv[threadIdx.x + s];
            int i2 = si[threadIdx.x + s];
            if (v2 > sv[threadIdx.x] ||
                (v2 == sv[threadIdx.x] && i2 < si[threadIdx.x])) {
                sv[threadIdx.x] = v2;
                si[threadIdx.x] = i2;
            }
        }
        __syncthreads();
    }
    if (threadIdx.x == 0) out_arg[row] = (float)si[0];
}

// ---------------- launch ------------------------------------------------------
extern "C" void kernel_launch(void* const* d_in, const int* in_sizes, int n_in,
                              void* d_out, int out_size) {
    const int*   topk = (const int*)d_in[0];     // [B,K]
    const float* img  = (const float*)d_in[1];   // [B,DI]
    const int*   seq  = (const int*)d_in[2];     // [B,T]
    const int*   len  = (const int*)d_in[3];     // [B]
    const float* wemb = (const float*)d_in[4];   // [V,DE]
    const float* aemb = (const float*)d_in[5];   // [1000,DA]
    const float* Wl   = (const float*)d_in[6];   // [DE+DI+DA+H, 4H]
    const float* bl   = (const float*)d_in[7];   // [4H]
    const float* Wlog = (const float*)d_in[8];   // [H,V]
    const float* blog = (const float*)d_in[9];   // [V]
    float* out = (float*)d_out;

    const int smem_lstm = Hh * Bb * 4 + 16 * 16 * ZPITCH * 8;  // 65536+34816
    cudaFuncSetAttribute(k_lstm, cudaFuncAttributeMaxDynamicSharedMemorySize,
                         smem_lstm);

    k_init<<<(Bb * FH) / 256, 256>>>(topk, aemb, bl);
    k_preb<<<dim3(FH / 128, 4), 128>>>(img, Wl);
    k_zpre<<<dim3(FH / 64, BT / 64), 256>>>(seq, wemb, Wl);
    k_lstm<<<NBLK, 256, smem_lstm>>>(Wl, len);
    k_logits<<<dim3(Vv / 64, BT / 128), 256>>>(Wlog, blog, out);
    if (out_size >= (long long)BT * Vv + BT)
        k_argmax<<<BT, 256>>>(out, out + (size_t)BT * Vv);
}

// round 16
// speedup vs baseline: 1.0773x; 1.0018x over previous
#include <cuda_runtime.h>
#include <math.h>

#define Bb 32
#define Tt 64
#define Kk 5
#define Vv 32000
#define DE 300
#define DA 300
#define DI 2048
#define Hh 512
#define FH 2048              // 4*H
#define HOFF (DE + DI + DA)  // 2648, row offset of h-part in lstm_kernel
#define BT (Bb * Tt)         // 2048
#define NBLK 128             // persistent LSTM blocks (<=148 SMs -> co-resident)

// ---------------- scratch (static device globals; no allocation) -------------
__device__ float g_mattr[Bb * DA];        // mean attribute embedding per batch
__device__ float g_preb[Bb * FH];         // bias + feats @ W_feats  [B,4H]
__device__ float g_zpre[BT * FH];         // + word_emb @ W_word     [B*T,4H] (16MB)
__device__ __align__(16) float g_hT[2][Hh * Bb];  // ping-pong h, TRANSPOSED [k][b]
__device__ float g_hseq[BT * Hh];         // masked h outputs (4MB)
__device__ unsigned g_barctr;             // grid barrier counter (reset in k_init)

// ---------------- f32x2 packed helpers (sm_103a FFMA2 path) ------------------
__device__ __forceinline__ unsigned long long pk2(float lo, float hi) {
    unsigned long long r;
    asm("mov.b64 %0, {%1, %2};" : "=l"(r) : "f"(lo), "f"(hi));
    return r;
}
__device__ __forceinline__ void fma2(unsigned long long& d,
                                     unsigned long long a,
                                     unsigned long long b) {
    asm("fma.rn.f32x2 %0, %1, %2, %0;" : "+l"(d) : "l"(a), "l"(b));
}
__device__ __forceinline__ float lo2(unsigned long long v) {
    return __uint_as_float((unsigned)(v & 0xffffffffull));
}
__device__ __forceinline__ float hi2(unsigned long long v) {
    return __uint_as_float((unsigned)(v >> 32));
}

// ---------------- kernel 0: init states, bias broadcast, mean attr -----------
__global__ void k_init(const int* __restrict__ topk,
                       const float* __restrict__ attr_emb,
                       const float* __restrict__ bias) {
    int idx = blockIdx.x * 256 + threadIdx.x;           // 0 .. Bb*FH-1
    g_preb[idx] = bias[idx & (FH - 1)];
    if (idx < Hh * Bb) g_hT[0][idx] = 0.f;
    if (idx == 0) g_barctr = 0u;
    if (idx < Bb * DA) {
        int b = idx / DA, d = idx - b * DA;
        float s = 0.f;
#pragma unroll
        for (int k = 0; k < Kk; k++)
            s += attr_emb[topk[b * Kk + k] * DA + d];
        g_mattr[idx] = s * (1.0f / Kk);
    }
}

// ---------------- kernel 1: g_preb += [img, mean_attr] @ W -------------------
__global__ void __launch_bounds__(128) k_preb(const float* __restrict__ img,
                                              const float* __restrict__ Wl) {
    __shared__ float sm[8][32];
    int j = blockIdx.x * 128 + threadIdx.x;
    int b0 = blockIdx.y * 8;
    float acc[8];
#pragma unroll
    for (int b = 0; b < 8; b++) acc[b] = 0.f;

    for (int d0 = 0; d0 < DI; d0 += 32) {
#pragma unroll
        for (int i = 0; i < 2; i++) {
            int e = threadIdx.x + i * 128;
            int bb = e >> 5, dc = e & 31;
            sm[bb][dc] = img[(b0 + bb) * DI + d0 + dc];
        }
        __syncthreads();
#pragma unroll 4
        for (int dc = 0; dc < 32; dc++) {
            float w = Wl[(size_t)(DE + d0 + dc) * FH + j];
#pragma unroll
            for (int b = 0; b < 8; b++) acc[b] += sm[b][dc] * w;
        }
        __syncthreads();
    }
    for (int d0 = 0; d0 < DA; d0 += 32) {
        int lim = DA - d0; if (lim > 32) lim = 32;
#pragma unroll
        for (int i = 0; i < 2; i++) {
            int e = threadIdx.x + i * 128;
            int bb = e >> 5, dc = e & 31;
            sm[bb][dc] = (dc < lim) ? g_mattr[(b0 + bb) * DA + d0 + dc] : 0.f;
        }
        __syncthreads();
        for (int dc = 0; dc < lim; dc++) {
            float w = Wl[(size_t)(DE + DI + d0 + dc) * FH + j];
#pragma unroll
            for (int b = 0; b < 8; b++) acc[b] += sm[b][dc] * w;
        }
        __syncthreads();
    }
#pragma unroll
    for (int b = 0; b < 8; b++)
        g_preb[(b0 + b) * FH + j] += acc[b];
}

// ---------------- kernel 2: g_zpre = gather(word_emb) @ W_word + g_preb ------
__global__ void __launch_bounds__(256) k_zpre(const int* __restrict__ seq,
                                              const float* __restrict__ wemb,
                                              const float* __restrict__ Wl) {
    __shared__ float As[20 * 68];
    __shared__ float Bs[20 * 64];
    __shared__ int sidx[64];
    int tid = threadIdx.x;
    int mbase = blockIdx.y * 64, nbase = blockIdx.x * 64;
    if (tid < 64) sidx[tid] = seq[mbase + tid];

    float acc[4][4];
#pragma unroll
    for (int i = 0; i < 4; i++)
#pragma unroll
        for (int j = 0; j < 4; j++) acc[i][j] = 0.f;

    int tm = (tid >> 4) * 4, tn = (tid & 15) * 4;

    for (int k0 = 0; k0 < 300; k0 += 20) {
        __syncthreads();
#pragma unroll
        for (int i = 0; i < 5; i++) {
            int e = tid + i * 256;
            int m = e / 20, kk = e - m * 20;
            As[kk * 68 + m] = wemb[(size_t)sidx[m] * DE + k0 + kk];
        }
#pragma unroll
        for (int i = 0; i < 5; i++) {
            int e = tid + i * 256;
            int kk = e >> 6, n = e & 63;
            Bs[kk * 64 + n] = Wl[(size_t)(k0 + kk) * FH + nbase + n];
        }
        __syncthreads();
#pragma unroll
        for (int kk = 0; kk < 20; kk++) {
            float4 a = *(const float4*)&As[kk * 68 + tm];
            float4 b = *(const float4*)&Bs[kk * 64 + tn];
            acc[0][0] += a.x * b.x; acc[0][1] += a.x * b.y; acc[0][2] += a.x * b.z; acc[0][3] += a.x * b.w;
            acc[1][0] += a.y * b.x; acc[1][1] += a.y * b.y; acc[1][2] += a.y * b.z; acc[1][3] += a.y * b.w;
            acc[2][0] += a.z * b.x; acc[2][1] += a.z * b.y; acc[2][2] += a.z * b.z; acc[2][3] += a.z * b.w;
            acc[3][0] += a.w * b.x; acc[3][1] += a.w * b.y; acc[3][2] += a.w * b.z; acc[3][3] += a.w * b.w;
        }
    }
#pragma unroll
    for (int mi = 0; mi < 4; mi++) {
        int row = mbase + tm + mi;
        int b = row >> 6;
        float4 pv = *(const float4*)&g_preb[b * FH + nbase + tn];
        float4 v = { acc[mi][0] + pv.x, acc[mi][1] + pv.y,
                     acc[mi][2] + pv.z, acc[mi][3] + pv.w };
        *(float4*)&g_zpre[(size_t)row * FH + nbase + tn] = v;
    }
}

// ---------------- kernel 3: PERSISTENT LSTM (all 64 steps, one launch) -------
// 128 blocks x 256 threads; block owns 4 units x 4 gates (16 cols of FH).
// W_h slice lives in registers (32/thread). h ping-pongs in global, TRANSPOSED
// [k][b] so staging loads are pure float4 copies and compute reads packed
// batch-pairs for f32x2 FMA. One software grid barrier per step.
// dyn smem: h_s 512*32 f32 (64KB) + zred 256 rows * 17 u64 (34KB) = 100352 B
#define ZPITCH 17  // u64 pitch per (c,ks) row: kills bank conflicts
__device__ __forceinline__ void grid_bar(int tid, unsigned target) {
    __threadfence();
    __syncthreads();
    if (tid == 0) {
        atomicAdd(&g_barctr, 1u);
        while (*((volatile unsigned*)&g_barctr) < target) __nanosleep(32);
        __threadfence();
    }
    __syncthreads();
}

__global__ void __launch_bounds__(256, 1) k_lstm(const float* __restrict__ Wl,
                                                 const int* __restrict__ lengths) {
    extern __shared__ float smdyn[];
    float* h_s = smdyn;                                  // [512][32]
    unsigned long long* zred = (unsigned long long*)(smdyn + Hh * Bb);

    int tid = threadIdx.x, blk = blockIdx.x;
    int c = tid & 15, ks = tid >> 4;                     // col-in-block, k-slice
    int gg = c >> 2, uu = c & 3;
    int jcol = gg * Hh + blk * 4 + uu;                   // column in FH
    int kb = ks * 32;                                    // k-slice base

    // preload W_h slice into registers (once; W_h read from DRAM exactly once)
    float w[32];
#pragma unroll
    for (int i = 0; i < 32; i++)
        w[i] = Wl[(size_t)(HOFF + kb + i) * FH + jcol];

    // fusion-thread state (tid < 128): unit fu, batch fb, c-state in register
    int fu = tid >> 5, fb = tid & 31;
    int u = blk * 4 + fu;
    float cstate = 0.f;
    int mylen = (tid < 128) ? lengths[fb] : 0;

    const float* zf = (const float*)zred;                // float view of partials

    for (int t = 0; t < Tt; t++) {
        // ---- stage h (transposed, packed) into smem: linear float4 copy ----
        const float4* src = (const float4*)g_hT[t & 1];
        float4* dst = (float4*)h_s;
#pragma unroll
        for (int i = 0; i < 16; i++)
            dst[tid + i * 256] = src[tid + i * 256];
        __syncthreads();

        // ---- compute partial z: 16 batch-pairs, k-slice of 32, f32x2 FMA ----
        unsigned long long acc[16];
#pragma unroll
        for (int bp = 0; bp < 16; bp++) acc[bp] = 0ull;
#pragma unroll
        for (int kk = 0; kk < 32; kk++) {
            unsigned long long wd = pk2(w[kk], w[kk]);
            const ulonglong2* hr = (const ulonglong2*)(h_s + (kb + kk) * Bb);
#pragma unroll
            for (int i = 0; i < 8; i++) {
                ulonglong2 hv = hr[i];
                fma2(acc[2 * i], hv.x, wd);
                fma2(acc[2 * i + 1], hv.y, wd);
            }
        }
        unsigned long long* zr = zred + (size_t)(c * 16 + ks) * ZPITCH;
#pragma unroll
        for (int bp = 0; bp < 16; bp++) zr[bp] = acc[bp];
        __syncthreads();

        // ---- gate fusion: 128 threads = 4 units x 32 batches ----
        if (tid < 128) {
            const float* zp = g_zpre + (size_t)(fb * Tt + t) * FH;
            float s[4];
#pragma unroll
            for (int g = 0; g < 4; g++) {
                float a = 0.f;
                int base = ((g * 4 + fu) * 16) * (2 * ZPITCH) + fb;
#pragma unroll
                for (int k2 = 0; k2 < 16; k2++)
                    a += zf[base + k2 * (2 * ZPITCH)];
                s[g] = a + zp[g * Hh + u];
            }
            float si = 1.f / (1.f + expf(-s[0]));
            float sf = 1.f / (1.f + expf(-s[1]));
            float so = 1.f / (1.f + expf(-s[3]));
            cstate = sf * cstate + si * tanhf(s[2]);
            float h2 = so * tanhf(cstate);
            g_hT[(t + 1) & 1][u * Bb + fb] = h2;         // transposed for next step
            g_hseq[(size_t)(fb * Tt + t) * Hh + u] = (t < mylen) ? h2 : 0.f;
        }

        if (t != Tt - 1) grid_bar(tid, (unsigned)(NBLK * (t + 1)));
    }
}

// ---------------- kernel 4: logits = h_seq @ W_logits + b --------------------
__global__ void __launch_bounds__(256) k_logits(const float* __restrict__ Wlog,
                                                const float* __restrict__ blog,
                                                float* __restrict__ out) {
    __shared__ float As[16 * 132];
    __shared__ float Bs[16 * 64];
    int tid = threadIdx.x;
    int nb = blockIdx.x * 64, mb = blockIdx.y * 128;
    int tm = (tid >> 4) * 8, tn = (tid & 15) * 4;

    unsigned long long acc[4][4];
#pragma unroll
    for (int i = 0; i < 4; i++)
#pragma unroll
        for (int j = 0; j < 4; j++) acc[i][j] = 0ull;

    for (int k0 = 0; k0 < Hh; k0 += 16) {
        __syncthreads();
#pragma unroll
        for (int i = 0; i < 8; i++) {
            int e = tid + i * 256;
            int m = e >> 4, kk = e & 15;
            As[kk * 132 + m] = g_hseq[(size_t)(mb + m) * Hh + k0 + kk];
        }
#pragma unroll
        for (int i = 0; i < 4; i++) {
            int e = tid + i * 256;
            int kk = e >> 6, n = e & 63;
            Bs[kk * 64 + n] = Wlog[(size_t)(k0 + kk) * Vv + nb + n];
        }
        __syncthreads();
#pragma unroll
        for (int kk = 0; kk < 16; kk++) {
            const unsigned long long* ap =
                (const unsigned long long*)&As[kk * 132 + tm];
            unsigned long long a0 = ap[0], a1 = ap[1], a2 = ap[2], a3 = ap[3];
            float4 bv = *(const float4*)&Bs[kk * 64 + tn];
            unsigned long long b0 = pk2(bv.x, bv.x), b1 = pk2(bv.y, bv.y);
            unsigned long long b2 = pk2(bv.z, bv.z), b3 = pk2(bv.w, bv.w);
            fma2(acc[0][0], a0, b0); fma2(acc[0][1], a0, b1);
            fma2(acc[0][2], a0, b2); fma2(acc[0][3], a0, b3);
            fma2(acc[1][0], a1, b0); fma2(acc[1][1], a1, b1);
            fma2(acc[1][2], a1, b2); fma2(acc[1][3], a1, b3);
            fma2(acc[2][0], a2, b0); fma2(acc[2][1], a2, b1);
            fma2(acc[2][2], a2, b2); fma2(acc[2][3], a2, b3);
            fma2(acc[3][0], a3, b0); fma2(acc[3][1], a3, b1);
            fma2(acc[3][2], a3, b2); fma2(acc[3][3], a3, b3);
        }
    }
    float4 bias = *(const float4*)&blog[nb + tn];
#pragma unroll
    for (int mp = 0; mp < 4; mp++) {
        int r0 = mb + tm + 2 * mp;
        float4 v0 = { lo2(acc[mp][0]) + bias.x, lo2(acc[mp][1]) + bias.y,
                      lo2(acc[mp][2]) + bias.z, lo2(acc[mp][3]) + bias.w };
        float4 v1 = { hi2(acc[mp][0]) + bias.x, hi2(acc[mp][1]) + bias.y,
                      hi2(acc[mp][2]) + bias.z, hi2(acc[mp][3]) + bias.w };
        *(float4*)&out[(size_t)r0 * Vv + nb + tn] = v0;
        *(float4*)&out[(size_t)(r0 + 1) * Vv + nb + tn] = v1;
    }
}

// ---------------- kernel 5: row-wise argmax (first-max tie-break) ------------
__global__ void __launch_bounds__(256) k_argmax(const float* __restrict__ logits,
                                                float* __restrict__ out_arg) {
    __shared__ float sv[256];
    __shared__ int si[256];
    int row = blockIdx.x;
    const float* p = logits + (size_t)row * Vv;
    float best = -INFINITY;
    int bi = 0;
    for (int c = threadIdx.x; c < Vv; c += 256) {
        float v = p[c];
        if (v > best) { best = v; bi = c; }
    }
    sv[threadIdx.x] = best;
    si[threadIdx.x] = bi;
    __syncthreads();
    for (int s = 128; s > 0; s >>= 1) {
        if (threadIdx.x < s) {
            float v2 = sv[threadIdx.x + s];
            int i2 = si[threadIdx.x + s];
            if (v2 > sv[threadIdx.x] ||
                (v2 == sv[threadIdx.x] && i2 < si[threadIdx.x])) {
                sv[threadIdx.x] = v2;
                si[threadIdx.x] = i2;
            }
        }
        __syncthreads();
    }
    if (threadIdx.x == 0) out_arg[row] = (float)si[0];
}

// ---------------- launch ------------------------------------------------------
extern "C" void kernel_launch(void* const* d_in, const int* in_sizes, int n_in,
                              void* d_out, int out_size) {
    const int*   topk = (const int*)d_in[0];     // [B,K]
    const float* img  = (const float*)d_in[1];   // [B,DI]
    const int*   seq  = (const int*)d_in[2];     // [B,T]
    const int*   len  = (const int*)d_in[3];     // [B]
    const float* wemb = (const float*)d_in[4];   // [V,DE]
    const float* aemb = (const float*)d_in[5];   // [1000,DA]
    const float* Wl   = (const float*)d_in[6];   // [DE+DI+DA+H, 4H]
    const float* bl   = (const float*)d_in[7];   // [4H]
    const float* Wlog = (const float*)d_in[8];   // [H,V]
    const float* blog = (const float*)d_in[9];   // [V]
    float* out = (float*)d_out;

    const int smem_lstm = Hh * Bb * 4 + 16 * 16 * ZPITCH * 8;  // 65536+34816
    cudaFuncSetAttribute(k_lstm, cudaFuncAttributeMaxDynamicSharedMemorySize,
                         smem_lstm);

    k_init<<<(Bb * FH) / 256, 256>>>(topk, aemb, bl);
    k_preb<<<dim3(FH / 128, 4), 128>>>(img, Wl);
    k_zpre<<<dim3(FH / 64, BT / 64), 256>>>(seq, wemb, Wl);
    k_lstm<<<NBLK, 256, smem_lstm>>>(Wl, len);
    k_logits<<<dim3(Vv / 64, BT / 128), 256>>>(Wlog, blog, out);
    if (out_size >= (long long)BT * Vv + BT)
        k_argmax<<<BT, 256>>>(out, out + (size_t)BT * Vv);
}